// round 1
// baseline (speedup 1.0000x reference)
#include <cuda_runtime.h>
#include <cuda_bf16.h>
#include <cstdint>

// Problem shapes (fixed for this dataset entry)
constexpr int B = 4;
constexpr int S = 4096;
constexpr int D = 2048;

constexpr int TT   = 64;   // t-tile per block
constexpr int HALO = 8;    // recurrence depth N_BLANKS
constexpr int THREADS = D / 4;  // 512 threads, one float4 lane each

__global__ __launch_bounds__(THREADS, 2)
void blank_embedding_kernel(const int* __restrict__ x,
                            const float* __restrict__ emb,
                            float* __restrict__ out)
{
    const int b  = blockIdx.y;
    const int T0 = blockIdx.x * TT;
    const int d4 = threadIdx.x;          // float4 index within D-row

    __shared__ int   sidx[TT + HALO];        // gather index for t in [T0-HALO, T0+TT)
    __shared__ float sp[TT + 2 * HALO];      // p[t] for t in [T0-2*HALO, T0+TT)

    // Stage indices
    for (int i = threadIdx.x; i < TT + HALO; i += blockDim.x) {
        int t = T0 - HALO + i;
        sidx[i] = (t >= 0) ? x[b * S + t] : 0;
    }
    // Stage p[t] = (x[t+1] < 16) && (x[t] >= 16); zero outside [0, S-1)
    for (int i = threadIdx.x; i < TT + 2 * HALO; i += blockDim.x) {
        int t = T0 - 2 * HALO + i;
        float pv = 0.0f;
        if (t >= 0 && t + 1 < S) {
            int xt  = x[b * S + t];
            int xt1 = x[b * S + t + 1];
            pv = (xt1 < 16 && xt >= 16) ? 1.0f : 0.0f;
        }
        sp[i] = pv;
    }
    __syncthreads();

    // prev[k] holds out_k[t-1] for k = 0..7 (out_8 never feeds back)
    float4 prev[8];
#pragma unroll
    for (int k = 0; k < 8; k++) prev[k] = make_float4(0.f, 0.f, 0.f, 0.f);

    // Rolling window: pw[k-1] = p[t-k]. Initialize for t = T0 - HALO.
    // sp index of global t' is t' - (T0 - 2*HALO); for t' = T0-HALO-k -> HALO-k.
    float pw[8];
    unsigned mask = 0;
#pragma unroll
    for (int k = 1; k <= 8; k++) {
        pw[k - 1] = sp[HALO - k];
        if (pw[k - 1] != 0.0f) mask |= (1u << (k - 1));
    }

    float* outb = out + ((size_t)b * S) * D + (size_t)d4 * 4;

    for (int i = 0; i < TT + HALO; i++) {
        const int t = T0 - HALO + i;
        if (t >= 0) {
            const int idx = sidx[i];
            const float4 e = *reinterpret_cast<const float4*>(emb + (size_t)idx * D + (size_t)d4 * 4);
            float4 c = e;
            if (mask) {
#pragma unroll
                for (int k = 0; k < 8; k++) {
                    float4 tmp = c;                 // out_k[t]
                    float  pv  = pw[k];             // p[t-(k+1)]
                    c.x = fmaf(prev[k].x, pv, c.x);
                    c.y = fmaf(prev[k].y, pv, c.y);
                    c.z = fmaf(prev[k].z, pv, c.z);
                    c.w = fmaf(prev[k].w, pv, c.w);
                    prev[k] = tmp;                  // becomes out_k[t] for next t
                }
            } else {
                // all p in window zero: out_k[t] = e for all k
#pragma unroll
                for (int k = 0; k < 8; k++) prev[k] = e;
            }
            if (t >= T0) {
                *reinterpret_cast<float4*>(outb + (size_t)t * D) = c;
            }
        }
        // advance window: next iteration's p[t'-1] is p[t]
        const float pn = sp[i + HALO];
#pragma unroll
        for (int k = 7; k > 0; k--) pw[k] = pw[k - 1];
        pw[0] = pn;
        mask = ((mask << 1) | (pn != 0.0f ? 1u : 0u)) & 0xFFu;
    }
}

extern "C" void kernel_launch(void* const* d_in, const int* in_sizes, int n_in,
                              void* d_out, int out_size)
{
    const int*   x   = (const int*)d_in[0];
    const float* emb = (const float*)d_in[1];
    float*       out = (float*)d_out;

    dim3 grid(S / TT, B);   // 64 x 4 = 256 blocks
    blank_embedding_kernel<<<grid, THREADS>>>(x, emb, out);
}

// round 2
// speedup vs baseline: 1.9659x; 1.9659x over previous
#include <cuda_runtime.h>
#include <cuda_bf16.h>
#include <cstdint>

// Problem shapes (fixed for this dataset entry)
constexpr int B = 4;
constexpr int S = 4096;
constexpr int D = 2048;

constexpr int TT   = 64;   // t-tile per block
constexpr int HALO = 8;    // recurrence depth N_BLANKS
constexpr int LEAD = 4;    // load prefetch distance (iterations)
constexpr int THREADS = D / 4;  // 512 threads, one float4 lane each

__global__ __launch_bounds__(THREADS, 2)
void blank_embedding_kernel(const int* __restrict__ x,
                            const float* __restrict__ emb,
                            float* __restrict__ out)
{
    const int b   = blockIdx.y;
    const int T0  = blockIdx.x * TT;
    const int tid = threadIdx.x;
    const int d4  = tid;                 // float4 index within D-row

    // sidx[i] = gather index for global t = T0 - HALO + i, i in [0, TT+HALO+LEAD)
    __shared__ int      sidx[TT + HALO + LEAD];
    // sp[i] = p[t] for t = T0 - 2*HALO + i
    __shared__ float    sp[TT + 2 * HALO];
    // weight DP buffers: wbuf[lvl&1][pos][j-1], pos owns t = T0 - HALO + pos
    __shared__ float    wbuf[2][TT + HALO][HALO];
    // per-output nonzero-weight bitmask (bits 1..8); 0 => fast path
    __shared__ unsigned sflag[TT];

    // ---- stage gather indices (clamped; weights guarantee halo/overread terms are 0) ----
    for (int i = tid; i < TT + HALO + LEAD; i += THREADS) {
        int t = T0 - HALO + i;
        t = max(0, min(t, S - 1));
        sidx[i] = x[b * S + t];
    }
    // ---- stage p[t] = (x[t+1] < 16) && (x[t] >= 16), zero outside [0, S-1) ----
    for (int i = tid; i < TT + 2 * HALO; i += THREADS) {
        int t = T0 - 2 * HALO + i;
        float pv = 0.0f;
        if (t >= 0 && t + 1 < S) {
            int xt  = x[b * S + t];
            int xt1 = x[b * S + t + 1];
            pv = (xt1 < 16 && xt >= 16) ? 1.0f : 0.0f;
        }
        sp[i] = pv;
    }
    __syncthreads();

    // ---- cooperative weight DP: w^k[t][j] = w^{k-1}[t][j] + p[t-k] * w^{k-1}[t-1][j-1]
    //      (w_0 is identically 1 and kept implicit)                              ----
    float wloc[HALO];
#pragma unroll
    for (int j = 0; j < HALO; j++) wloc[j] = 0.0f;

    if (tid < TT + HALO) {
#pragma unroll
        for (int j = 0; j < HALO; j++) wbuf[0][tid][j] = 0.0f;
    }
    __syncthreads();

    for (int k = 1; k <= HALO; k++) {
        const int cur = k & 1, prv = cur ^ 1;
        float nb[HALO];          // neighbor's previous-level w_{j}, j=0..7 (w0 implicit)
        float nb0 = 0.0f;
        if (tid < TT + HALO) {
            if (tid > 0) {
                nb0 = 1.0f;      // neighbor's w_0
#pragma unroll
                for (int j = 0; j < HALO - 1; j++) nb[j] = wbuf[prv][tid - 1][j];
            } else {
#pragma unroll
                for (int j = 0; j < HALO - 1; j++) nb[j] = 0.0f;
            }
            const float pv = sp[tid + HALO - k];
            // j = 1 uses neighbor w_0; j >= 2 uses neighbor w_{j-1}
            wloc[0] = fmaf(pv, nb0, wloc[0]);
#pragma unroll
            for (int j = 1; j < HALO; j++) wloc[j] = fmaf(pv, nb[j - 1], wloc[j]);
#pragma unroll
            for (int j = 0; j < HALO; j++) wbuf[cur][tid][j] = wloc[j];
        }
        __syncthreads();
    }
    // final level k=8 -> buffer index 0
    if (tid >= HALO && tid < TT + HALO) {
        unsigned m = 0;
#pragma unroll
        for (int j = 0; j < HALO; j++)
            if (wbuf[0][tid][j] != 0.0f) m |= (1u << (j + 1));
        sflag[tid - HALO] = m;
    }
    __syncthreads();

    // ---- main streaming loop: out[t] = e[t] + sum_j w_j * e[t-j] ----
    const float* embp = emb + (size_t)d4 * 4;
    float*       outp = out + ((size_t)(b * S + T0)) * D + (size_t)d4 * 4;

    float4 pipe[LEAD];
#pragma unroll
    for (int u = 0; u < LEAD; u++)
        pipe[u] = *reinterpret_cast<const float4*>(embp + (size_t)sidx[HALO + u] * D);

    for (int g = 0; g < TT / LEAD; g++) {
#pragma unroll
        for (int u = 0; u < LEAD; u++) {
            const int i = g * LEAD + u;
            float4 c = pipe[u];
            // issue prefetch for i+LEAD immediately (sidx padded, always safe)
            pipe[u] = *reinterpret_cast<const float4*>(
                embp + (size_t)sidx[HALO + i + LEAD] * D);

            const unsigned m = sflag[i];
            if (m) {
#pragma unroll
                for (int j = 1; j <= HALO; j++) {
                    if (m & (1u << j)) {
                        const float w = wbuf[0][i + HALO][j - 1];
                        const float4 h = *reinterpret_cast<const float4*>(
                            embp + (size_t)sidx[HALO + i - j] * D);
                        c.x = fmaf(h.x, w, c.x);
                        c.y = fmaf(h.y, w, c.y);
                        c.z = fmaf(h.z, w, c.z);
                        c.w = fmaf(h.w, w, c.w);
                    }
                }
            }
            *reinterpret_cast<float4*>(outp + (size_t)i * D) = c;
        }
    }
}

extern "C" void kernel_launch(void* const* d_in, const int* in_sizes, int n_in,
                              void* d_out, int out_size)
{
    const int*   x   = (const int*)d_in[0];
    const float* emb = (const float*)d_in[1];
    float*       out = (float*)d_out;

    dim3 grid(S / TT, B);   // 64 x 4 = 256 blocks
    blank_embedding_kernel<<<grid, THREADS>>>(x, emb, out);
}